// round 13
// baseline (speedup 1.0000x reference)
#include <cuda_runtime.h>
#include <math.h>
#include <stdint.h>

#define BATCH   2
#define DMODEL  1024
#define SPLIT   64
#define KTOP    7

#define CHUNK   32
#define NCHUNK  (DMODEL / CHUNK)      // 32
#define APITCH  36                    // floats per smem row (conflict-free)
#define AROWS   256                   // 4 splits per CTA
#define BROWS   64
#define AFLOATS (AROWS * APITCH)      // 9216
#define BFLOATS (BROWS * APITCH)      // 2304
#define DYNF    (2 * (AFLOATS + BFLOATS))
#define DYNB    (DYNF * 4)            // 92160 bytes

// Scratch (device globals; no allocation allowed)
__device__ float g_scores[BATCH * 2048];

__device__ __forceinline__ uint32_t smem_u32(const void* p) {
    uint32_t a;
    asm("{ .reg .u64 t; cvta.to.shared.u64 t, %1; cvt.u32.u64 %0, t; }"
        : "=r"(a) : "l"(p));
    return a;
}
__device__ __forceinline__ void cp16(uint32_t dst, const void* src) {
    asm volatile("cp.async.cg.shared.global [%0], [%1], 16;"
                 :: "r"(dst), "l"(src) : "memory");
}

// ---------------------------------------------------------------------------
// Kernel B: tf32 mma.sync GEMM. Per CTA: batch b, splits 4x..4x+3.
//   A = prev rows [row0 .. row0+255]  (M = 256)
//   B = cur rows  [0 .. 63]           (N = 64)
// Row norms (both prev and cur) are accumulated IN REGISTERS from the MMA
// fragments themselves (each warp's fragments cover its A sub-tile rows and
// all 64 B rows exactly once per K-chunk) -> no extra smem reads, no
// separate curnorm kernel.
// ---------------------------------------------------------------------------
__global__ void __launch_bounds__(256, 2)
sim_mma_kernel(const float* __restrict__ emb, int csi) {
    extern __shared__ float sm[];
    __shared__ float sinvp[256];      // prev-row inverse norms
    __shared__ float sinvq[64];       // cur-row inverse norms
    __shared__ float wcolmax[8][64];
    __shared__ float partial[8];

    int tid = threadIdx.x;
    int w = tid >> 5, lane = tid & 31, g = lane >> 2, c = lane & 3;
    int b = blockIdx.y;
    int row0 = blockIdx.x * 256;
    int maxrow = csi * SPLIT - 1;

    const float* base = emb + (size_t)b * (csi + 1) * SPLIT * DMODEL;
    const float* curp = base + (size_t)csi * SPLIT * DMODEL;

    // A source row for this thread (clamped; clamped rows land in splits
    // >= csi which are never emitted)
    int arow = row0 + tid;
    if (arow > maxrow) arow = maxrow;
    const float* asrc = base + (size_t)arow * DMODEL;

    uint32_t sm_u = smem_u32(sm);

    float acc[2][8][4];
    #pragma unroll
    for (int i = 0; i < 2; i++)
        #pragma unroll
        for (int j = 0; j < 8; j++)
            #pragma unroll
            for (int x = 0; x < 4; x++) acc[i][j][x] = 0.f;

    // fragment-derived sumsq accumulators
    float ssqA[2][2] = {{0.f, 0.f}, {0.f, 0.f}};   // rows w*32+16i+g, +8
    float ssqB[8];                                  // rows 8j+g
    #pragma unroll
    for (int j = 0; j < 8; j++) ssqB[j] = 0.f;

    auto load_chunk = [&](int it, int pbuf) {
        int kk = it * CHUNK;
        // A: 256 rows x 32 cols; thread = one row, 8 x 16B
        uint32_t adst = sm_u + (uint32_t)(pbuf * AFLOATS + tid * APITCH) * 4;
        #pragma unroll
        for (int j = 0; j < 8; j++)
            cp16(adst + j * 16, asrc + kk + j * 4);
        // B: 64 rows x 32 cols; 512 x 16B over 256 threads
        uint32_t bbase = sm_u + (uint32_t)(2 * AFLOATS + pbuf * BFLOATS) * 4;
        #pragma unroll
        for (int u = 0; u < 2; u++) {
            int idx = tid + u * 256;
            int n = idx >> 3, j = idx & 7;
            cp16(bbase + (uint32_t)(n * APITCH + j * 4) * 4,
                 curp + (size_t)n * DMODEL + kk + j * 4);
        }
        asm volatile("cp.async.commit_group;" ::: "memory");
    };

    load_chunk(0, 0);

    for (int it = 0; it < NCHUNK; it++) {
        if (it + 1 < NCHUNK) {
            load_chunk(it + 1, (it + 1) & 1);
            asm volatile("cp.async.wait_group 1;" ::: "memory");
        } else {
            asm volatile("cp.async.wait_group 0;" ::: "memory");
        }
        __syncthreads();

        const float* Ab = sm + (it & 1) * AFLOATS;
        const float* Bb = sm + 2 * AFLOATS + (it & 1) * BFLOATS;
        const float* Aw = Ab + (w * 32) * APITCH;

        #pragma unroll
        for (int k4 = 0; k4 < 4; k4++) {
            int k0 = k4 * 8;
            uint32_t a[2][4];
            #pragma unroll
            for (int i = 0; i < 2; i++) {
                int rb = 16 * i + g;
                a[i][0] = __float_as_uint(Aw[rb * APITCH + k0 + c]);
                a[i][1] = __float_as_uint(Aw[(rb + 8) * APITCH + k0 + c]);
                a[i][2] = __float_as_uint(Aw[rb * APITCH + k0 + c + 4]);
                a[i][3] = __float_as_uint(Aw[(rb + 8) * APITCH + k0 + c + 4]);
                // fragment-derived prev-row sumsq (full fp32 values)
                float f0 = __uint_as_float(a[i][0]), f1 = __uint_as_float(a[i][1]);
                float f2 = __uint_as_float(a[i][2]), f3 = __uint_as_float(a[i][3]);
                ssqA[i][0] += f0 * f0 + f2 * f2;
                ssqA[i][1] += f1 * f1 + f3 * f3;
            }
            #pragma unroll
            for (int j = 0; j < 8; j++) {
                uint32_t b0 = __float_as_uint(Bb[(8 * j + g) * APITCH + k0 + c]);
                uint32_t b1 = __float_as_uint(Bb[(8 * j + g) * APITCH + k0 + c + 4]);
                float fb0 = __uint_as_float(b0), fb1 = __uint_as_float(b1);
                ssqB[j] += fb0 * fb0 + fb1 * fb1;
                #pragma unroll
                for (int i = 0; i < 2; i++) {
                    asm volatile(
                        "mma.sync.aligned.m16n8k8.row.col.f32.tf32.tf32.f32 "
                        "{%0,%1,%2,%3}, {%4,%5,%6,%7}, {%8,%9}, {%0,%1,%2,%3};"
                        : "+f"(acc[i][j][0]), "+f"(acc[i][j][1]),
                          "+f"(acc[i][j][2]), "+f"(acc[i][j][3])
                        : "r"(a[i][0]), "r"(a[i][1]), "r"(a[i][2]), "r"(a[i][3]),
                          "r"(b0), "r"(b1));
                }
            }
        }
        __syncthreads();
    }

    // Reduce fragment sumsq over the 4 c-lanes (same g) -> row norms.
    #pragma unroll
    for (int i = 0; i < 2; i++)
        #pragma unroll
        for (int h = 0; h < 2; h++) {
            float v = ssqA[i][h];
            v += __shfl_xor_sync(0xFFFFFFFF, v, 1);
            v += __shfl_xor_sync(0xFFFFFFFF, v, 2);
            ssqA[i][h] = v;
        }
    if (c == 0) {
        #pragma unroll
        for (int i = 0; i < 2; i++) {
            sinvp[w * 32 + 16 * i + g]     = 1.0f / fmaxf(sqrtf(ssqA[i][0]), 1e-12f);
            sinvp[w * 32 + 16 * i + g + 8] = 1.0f / fmaxf(sqrtf(ssqA[i][1]), 1e-12f);
        }
    }
    #pragma unroll
    for (int j = 0; j < 8; j++) {
        float v = ssqB[j];
        v += __shfl_xor_sync(0xFFFFFFFF, v, 1);
        v += __shfl_xor_sync(0xFFFFFFFF, v, 2);
        if (w == 0 && c == 0)
            sinvq[8 * j + g] = 1.0f / fmaxf(sqrtf(v), 1e-12f);
    }
    __syncthreads();

    // per-warp col maxima over its 32 rows (scaled by inv prev norm)
    #pragma unroll
    for (int j = 0; j < 8; j++) {
        #pragma unroll
        for (int cc = 0; cc < 2; cc++) {
            float m = -INFINITY;
            #pragma unroll
            for (int i = 0; i < 2; i++) {
                int r0 = w * 32 + 16 * i + g;
                m = fmaxf(m, acc[i][j][cc] * sinvp[r0]);
                m = fmaxf(m, acc[i][j][cc + 2] * sinvp[r0 + 8]);
            }
            m = fmaxf(m, __shfl_xor_sync(0xFFFFFFFF, m, 4));
            m = fmaxf(m, __shfl_xor_sync(0xFFFFFFFF, m, 8));
            m = fmaxf(m, __shfl_xor_sync(0xFFFFFFFF, m, 16));
            if (g == 0) wcolmax[w][8 * j + 2 * c + cc] = m;
        }
    }
    __syncthreads();

    // split scores: split s owns warps 2s, 2s+1 (rows 64s..64s+63)
    {
        int s = tid >> 6, q = tid & 63;
        float m = fmaxf(wcolmax[2 * s][q], wcolmax[2 * s + 1][q]);
        float val = m * sinvq[q];
        #pragma unroll
        for (int o = 16; o > 0; o >>= 1)
            val += __shfl_xor_sync(0xFFFFFFFF, val, o);
        if (lane == 0) partial[w] = val;
    }
    __syncthreads();
    if (tid < 4) {
        int n_global = blockIdx.x * 4 + tid;
        if (n_global < csi)
            g_scores[b * 2048 + n_global] = partial[2 * tid] + partial[2 * tid + 1];
    }
}

// ---------------------------------------------------------------------------
// Kernel C: top-k + flat float32 output [indices | weights]
// ---------------------------------------------------------------------------
__global__ void topk_kernel(float* __restrict__ out, int csi, int kact, int B) {
    int b = blockIdx.x;
    int tid = threadIdx.x;
    __shared__ float s[2048];
    __shared__ float rv[256];
    __shared__ int   ri[256];
    __shared__ float topv[KTOP + 1];
    __shared__ int   topi[KTOP + 1];

    for (int i = tid; i < csi; i += 256) s[i] = g_scores[b * 2048 + i];
    __syncthreads();

    for (int t = 0; t < kact; t++) {
        float bv = -INFINITY;
        int bi = 0x7FFFFFFF;
        for (int i = tid; i < csi; i += 256) {
            float v = s[i];
            if (v > bv) { bv = v; bi = i; }
        }
        rv[tid] = bv; ri[tid] = bi;
        __syncthreads();
        for (int str = 128; str > 0; str >>= 1) {
            if (tid < str) {
                if (rv[tid + str] > rv[tid] ||
                    (rv[tid + str] == rv[tid] && ri[tid + str] < ri[tid])) {
                    rv[tid] = rv[tid + str];
                    ri[tid] = ri[tid + str];
                }
            }
            __syncthreads();
        }
        if (tid == 0) {
            topv[t] = rv[0];
            topi[t] = ri[0];
            s[ri[0]] = -INFINITY;
        }
        __syncthreads();
    }

    if (tid == 0) {
        int width = kact + 1;
        int woff = B * width;
        float mx = topv[0];
        for (int j = 0; j < kact; j++) {
            out[b * width + j]        = (float)topi[j];
            out[woff + b * width + j] = topv[j] / (mx + 1e-8f);
        }
        out[b * width + kact]        = (float)csi;
        out[woff + b * width + kact] = 1.0f;
    }
}

// ---------------------------------------------------------------------------
extern "C" void kernel_launch(void* const* d_in, const int* in_sizes, int n_in,
                              void* d_out, int out_size) {
    const float* emb = (const float*)d_in[0];
    long long total = (long long)in_sizes[0];
    int n_avail = (int)(total / ((long long)BATCH * DMODEL * SPLIT));
    int csi = n_avail - 1;
    int kact = csi < KTOP ? csi : KTOP;

    cudaFuncSetAttribute(sim_mma_kernel,
                         cudaFuncAttributeMaxDynamicSharedMemorySize, DYNB);

    int nb = (csi + 3) / 4;                 // 4 splits per CTA
    dim3 gB(nb, BATCH);
    sim_mma_kernel<<<gB, 256, DYNB>>>(emb, csi);

    topk_kernel<<<BATCH, 256>>>((float*)d_out, csi, kact, BATCH);
}

// round 14
// speedup vs baseline: 1.0022x; 1.0022x over previous
#include <cuda_runtime.h>
#include <math.h>
#include <stdint.h>

#define BATCH   2
#define DMODEL  1024
#define SPLIT   64
#define KTOP    7

#define CHUNK   32
#define NCHUNK  (DMODEL / CHUNK)      // 32
#define APITCH  36                    // floats per smem row (conflict-free)
#define AROWS   256                   // 4 splits per CTA
#define BROWS   64
#define AFLOATS (AROWS * APITCH)      // 9216
#define BFLOATS (BROWS * APITCH)      // 2304
#define DYNF    (2 * (AFLOATS + BFLOATS))
#define DYNB    (DYNF * 4)            // 92160 bytes

// Scratch (device globals; no allocation allowed)
__device__ float g_scores[BATCH * 2048];

__device__ __forceinline__ uint32_t smem_u32(const void* p) {
    uint32_t a;
    asm("{ .reg .u64 t; cvta.to.shared.u64 t, %1; cvt.u32.u64 %0, t; }"
        : "=r"(a) : "l"(p));
    return a;
}
__device__ __forceinline__ void cp16(uint32_t dst, const void* src) {
    asm volatile("cp.async.cg.shared.global [%0], [%1], 16;"
                 :: "r"(dst), "l"(src) : "memory");
}

// ---------------------------------------------------------------------------
// Kernel B: tf32 mma.sync GEMM. Per CTA: batch b, splits 4x..4x+3.
//   A = prev rows [row0 .. row0+255]  (M = 256)
//   B = cur rows  [0 .. 63]           (N = 64)
// Row norms (both prev and cur) are accumulated IN REGISTERS from the MMA
// fragments themselves (each warp's fragments cover its A sub-tile rows and
// all 64 B rows exactly once per K-chunk) -> no extra smem reads, no
// separate curnorm kernel.
// ---------------------------------------------------------------------------
__global__ void __launch_bounds__(256, 2)
sim_mma_kernel(const float* __restrict__ emb, int csi) {
    extern __shared__ float sm[];
    __shared__ float sinvp[256];      // prev-row inverse norms
    __shared__ float sinvq[64];       // cur-row inverse norms
    __shared__ float wcolmax[8][64];
    __shared__ float partial[8];

    int tid = threadIdx.x;
    int w = tid >> 5, lane = tid & 31, g = lane >> 2, c = lane & 3;
    int b = blockIdx.y;
    int row0 = blockIdx.x * 256;
    int maxrow = csi * SPLIT - 1;

    const float* base = emb + (size_t)b * (csi + 1) * SPLIT * DMODEL;
    const float* curp = base + (size_t)csi * SPLIT * DMODEL;

    // A source row for this thread (clamped; clamped rows land in splits
    // >= csi which are never emitted)
    int arow = row0 + tid;
    if (arow > maxrow) arow = maxrow;
    const float* asrc = base + (size_t)arow * DMODEL;

    uint32_t sm_u = smem_u32(sm);

    float acc[2][8][4];
    #pragma unroll
    for (int i = 0; i < 2; i++)
        #pragma unroll
        for (int j = 0; j < 8; j++)
            #pragma unroll
            for (int x = 0; x < 4; x++) acc[i][j][x] = 0.f;

    // fragment-derived sumsq accumulators
    float ssqA[2][2] = {{0.f, 0.f}, {0.f, 0.f}};   // rows w*32+16i+g, +8
    float ssqB[8];                                  // rows 8j+g
    #pragma unroll
    for (int j = 0; j < 8; j++) ssqB[j] = 0.f;

    auto load_chunk = [&](int it, int pbuf) {
        int kk = it * CHUNK;
        // A: 256 rows x 32 cols; thread = one row, 8 x 16B
        uint32_t adst = sm_u + (uint32_t)(pbuf * AFLOATS + tid * APITCH) * 4;
        #pragma unroll
        for (int j = 0; j < 8; j++)
            cp16(adst + j * 16, asrc + kk + j * 4);
        // B: 64 rows x 32 cols; 512 x 16B over 256 threads
        uint32_t bbase = sm_u + (uint32_t)(2 * AFLOATS + pbuf * BFLOATS) * 4;
        #pragma unroll
        for (int u = 0; u < 2; u++) {
            int idx = tid + u * 256;
            int n = idx >> 3, j = idx & 7;
            cp16(bbase + (uint32_t)(n * APITCH + j * 4) * 4,
                 curp + (size_t)n * DMODEL + kk + j * 4);
        }
        asm volatile("cp.async.commit_group;" ::: "memory");
    };

    load_chunk(0, 0);

    for (int it = 0; it < NCHUNK; it++) {
        if (it + 1 < NCHUNK) {
            load_chunk(it + 1, (it + 1) & 1);
            asm volatile("cp.async.wait_group 1;" ::: "memory");
        } else {
            asm volatile("cp.async.wait_group 0;" ::: "memory");
        }
        __syncthreads();

        const float* Ab = sm + (it & 1) * AFLOATS;
        const float* Bb = sm + 2 * AFLOATS + (it & 1) * BFLOATS;
        const float* Aw = Ab + (w * 32) * APITCH;

        #pragma unroll
        for (int k4 = 0; k4 < 4; k4++) {
            int k0 = k4 * 8;
            uint32_t a[2][4];
            #pragma unroll
            for (int i = 0; i < 2; i++) {
                int rb = 16 * i + g;
                a[i][0] = __float_as_uint(Aw[rb * APITCH + k0 + c]);
                a[i][1] = __float_as_uint(Aw[(rb + 8) * APITCH + k0 + c]);
                a[i][2] = __float_as_uint(Aw[rb * APITCH + k0 + c + 4]);
                a[i][3] = __float_as_uint(Aw[(rb + 8) * APITCH + k0 + c + 4]);
                // fragment-derived prev-row sumsq (full fp32 values)
                float f0 = __uint_as_float(a[i][0]), f1 = __uint_as_float(a[i][1]);
                float f2 = __uint_as_float(a[i][2]), f3 = __uint_as_float(a[i][3]);
                ssqA[i][0] += f0 * f0 + f2 * f2;
                ssqA[i][1] += f1 * f1 + f3 * f3;
            }
            #pragma unroll
            for (int j = 0; j < 8; j++) {
                uint32_t b0 = __float_as_uint(Bb[(8 * j + g) * APITCH + k0 + c]);
                uint32_t b1 = __float_as_uint(Bb[(8 * j + g) * APITCH + k0 + c + 4]);
                float fb0 = __uint_as_float(b0), fb1 = __uint_as_float(b1);
                ssqB[j] += fb0 * fb0 + fb1 * fb1;
                #pragma unroll
                for (int i = 0; i < 2; i++) {
                    asm volatile(
                        "mma.sync.aligned.m16n8k8.row.col.f32.tf32.tf32.f32 "
                        "{%0,%1,%2,%3}, {%4,%5,%6,%7}, {%8,%9}, {%0,%1,%2,%3};"
                        : "+f"(acc[i][j][0]), "+f"(acc[i][j][1]),
                          "+f"(acc[i][j][2]), "+f"(acc[i][j][3])
                        : "r"(a[i][0]), "r"(a[i][1]), "r"(a[i][2]), "r"(a[i][3]),
                          "r"(b0), "r"(b1));
                }
            }
        }
        __syncthreads();
    }

    // Reduce fragment sumsq over the 4 c-lanes (same g) -> row norms.
    #pragma unroll
    for (int i = 0; i < 2; i++)
        #pragma unroll
        for (int h = 0; h < 2; h++) {
            float v = ssqA[i][h];
            v += __shfl_xor_sync(0xFFFFFFFF, v, 1);
            v += __shfl_xor_sync(0xFFFFFFFF, v, 2);
            ssqA[i][h] = v;
        }
    if (c == 0) {
        #pragma unroll
        for (int i = 0; i < 2; i++) {
            sinvp[w * 32 + 16 * i + g]     = 1.0f / fmaxf(sqrtf(ssqA[i][0]), 1e-12f);
            sinvp[w * 32 + 16 * i + g + 8] = 1.0f / fmaxf(sqrtf(ssqA[i][1]), 1e-12f);
        }
    }
    #pragma unroll
    for (int j = 0; j < 8; j++) {
        float v = ssqB[j];
        v += __shfl_xor_sync(0xFFFFFFFF, v, 1);
        v += __shfl_xor_sync(0xFFFFFFFF, v, 2);
        if (w == 0 && c == 0)
            sinvq[8 * j + g] = 1.0f / fmaxf(sqrtf(v), 1e-12f);
    }
    __syncthreads();

    // per-warp col maxima over its 32 rows (scaled by inv prev norm)
    #pragma unroll
    for (int j = 0; j < 8; j++) {
        #pragma unroll
        for (int cc = 0; cc < 2; cc++) {
            float m = -INFINITY;
            #pragma unroll
            for (int i = 0; i < 2; i++) {
                int r0 = w * 32 + 16 * i + g;
                m = fmaxf(m, acc[i][j][cc] * sinvp[r0]);
                m = fmaxf(m, acc[i][j][cc + 2] * sinvp[r0 + 8]);
            }
            m = fmaxf(m, __shfl_xor_sync(0xFFFFFFFF, m, 4));
            m = fmaxf(m, __shfl_xor_sync(0xFFFFFFFF, m, 8));
            m = fmaxf(m, __shfl_xor_sync(0xFFFFFFFF, m, 16));
            if (g == 0) wcolmax[w][8 * j + 2 * c + cc] = m;
        }
    }
    __syncthreads();

    // split scores: split s owns warps 2s, 2s+1 (rows 64s..64s+63)
    {
        int s = tid >> 6, q = tid & 63;
        float m = fmaxf(wcolmax[2 * s][q], wcolmax[2 * s + 1][q]);
        float val = m * sinvq[q];
        #pragma unroll
        for (int o = 16; o > 0; o >>= 1)
            val += __shfl_xor_sync(0xFFFFFFFF, val, o);
        if (lane == 0) partial[w] = val;
    }
    __syncthreads();
    if (tid < 4) {
        int n_global = blockIdx.x * 4 + tid;
        if (n_global < csi)
            g_scores[b * 2048 + n_global] = partial[2 * tid] + partial[2 * tid + 1];
    }
}

// ---------------------------------------------------------------------------
// Kernel C: top-k + flat float32 output [indices | weights]
// ---------------------------------------------------------------------------
__global__ void topk_kernel(float* __restrict__ out, int csi, int kact, int B) {
    int b = blockIdx.x;
    int tid = threadIdx.x;
    __shared__ float s[2048];
    __shared__ float rv[256];
    __shared__ int   ri[256];
    __shared__ float topv[KTOP + 1];
    __shared__ int   topi[KTOP + 1];

    for (int i = tid; i < csi; i += 256) s[i] = g_scores[b * 2048 + i];
    __syncthreads();

    for (int t = 0; t < kact; t++) {
        float bv = -INFINITY;
        int bi = 0x7FFFFFFF;
        for (int i = tid; i < csi; i += 256) {
            float v = s[i];
            if (v > bv) { bv = v; bi = i; }
        }
        rv[tid] = bv; ri[tid] = bi;
        __syncthreads();
        for (int str = 128; str > 0; str >>= 1) {
            if (tid < str) {
                if (rv[tid + str] > rv[tid] ||
                    (rv[tid + str] == rv[tid] && ri[tid + str] < ri[tid])) {
                    rv[tid] = rv[tid + str];
                    ri[tid] = ri[tid + str];
                }
            }
            __syncthreads();
        }
        if (tid == 0) {
            topv[t] = rv[0];
            topi[t] = ri[0];
            s[ri[0]] = -INFINITY;
        }
        __syncthreads();
    }

    if (tid == 0) {
        int width = kact + 1;
        int woff = B * width;
        float mx = topv[0];
        for (int j = 0; j < kact; j++) {
            out[b * width + j]        = (float)topi[j];
            out[woff + b * width + j] = topv[j] / (mx + 1e-8f);
        }
        out[b * width + kact]        = (float)csi;
        out[woff + b * width + kact] = 1.0f;
    }
}

// ---------------------------------------------------------------------------
extern "C" void kernel_launch(void* const* d_in, const int* in_sizes, int n_in,
                              void* d_out, int out_size) {
    const float* emb = (const float*)d_in[0];
    long long total = (long long)in_sizes[0];
    int n_avail = (int)(total / ((long long)BATCH * DMODEL * SPLIT));
    int csi = n_avail - 1;
    int kact = csi < KTOP ? csi : KTOP;

    cudaFuncSetAttribute(sim_mma_kernel,
                         cudaFuncAttributeMaxDynamicSharedMemorySize, DYNB);

    int nb = (csi + 3) / 4;                 // 4 splits per CTA
    dim3 gB(nb, BATCH);
    sim_mma_kernel<<<gB, 256, DYNB>>>(emb, csi);

    topk_kernel<<<BATCH, 256>>>((float*)d_out, csi, kact, BATCH);
}

// round 16
// speedup vs baseline: 1.0034x; 1.0012x over previous
#include <cuda_runtime.h>
#include <math.h>
#include <stdint.h>

#define BATCH   2
#define DMODEL  1024
#define SPLIT   64
#define KTOP    7

#define CHUNK   32
#define NCHUNK  (DMODEL / CHUNK)      // 32
#define APITCH  36                    // floats per smem row (conflict-free)
#define AROWS   256                   // 4 splits per CTA
#define BROWS   64
#define AFLOATS (AROWS * APITCH)      // 9216
#define BFLOATS (BROWS * APITCH)      // 2304
#define DYNF    (2 * (AFLOATS + BFLOATS))
#define DYNB    (DYNF * 4)            // 92160 bytes

// Scratch (device globals; no allocation allowed)
__device__ float g_scores[BATCH * 2048];

__device__ __forceinline__ uint32_t smem_u32(const void* p) {
    uint32_t a;
    asm("{ .reg .u64 t; cvta.to.shared.u64 t, %1; cvt.u32.u64 %0, t; }"
        : "=r"(a) : "l"(p));
    return a;
}
__device__ __forceinline__ void cp16(uint32_t dst, const void* src) {
    asm volatile("cp.async.cg.shared.global [%0], [%1], 16;"
                 :: "r"(dst), "l"(src) : "memory");
}

// ---------------------------------------------------------------------------
// Kernel B: tf32 mma.sync GEMM. Per CTA: batch b, splits 4x..4x+3.
//   A = prev rows [row0 .. row0+255]  (M = 256)
//   B = cur rows  [0 .. 63]           (N = 64)
// Row norms (both prev and cur) are accumulated IN REGISTERS from the MMA
// fragments themselves (each warp's fragments cover its A sub-tile rows and
// all 64 B rows exactly once per K-chunk) -> no extra smem reads, no
// separate curnorm kernel.
// ---------------------------------------------------------------------------
__global__ void __launch_bounds__(256, 2)
sim_mma_kernel(const float* __restrict__ emb, int csi) {
    extern __shared__ float sm[];
    __shared__ float sinvp[256];      // prev-row inverse norms
    __shared__ float sinvq[64];       // cur-row inverse norms
    __shared__ float wcolmax[8][64];
    __shared__ float partial[8];

    int tid = threadIdx.x;
    int w = tid >> 5, lane = tid & 31, g = lane >> 2, c = lane & 3;
    int b = blockIdx.y;
    int row0 = blockIdx.x * 256;
    int maxrow = csi * SPLIT - 1;

    const float* base = emb + (size_t)b * (csi + 1) * SPLIT * DMODEL;
    const float* curp = base + (size_t)csi * SPLIT * DMODEL;

    // A source row for this thread (clamped; clamped rows land in splits
    // >= csi which are never emitted)
    int arow = row0 + tid;
    if (arow > maxrow) arow = maxrow;
    const float* asrc = base + (size_t)arow * DMODEL;

    uint32_t sm_u = smem_u32(sm);

    float acc[2][8][4];
    #pragma unroll
    for (int i = 0; i < 2; i++)
        #pragma unroll
        for (int j = 0; j < 8; j++)
            #pragma unroll
            for (int x = 0; x < 4; x++) acc[i][j][x] = 0.f;

    // fragment-derived sumsq accumulators
    float ssqA[2][2] = {{0.f, 0.f}, {0.f, 0.f}};   // rows w*32+16i+g, +8
    float ssqB[8];                                  // rows 8j+g
    #pragma unroll
    for (int j = 0; j < 8; j++) ssqB[j] = 0.f;

    auto load_chunk = [&](int it, int pbuf) {
        int kk = it * CHUNK;
        // A: 256 rows x 32 cols; thread = one row, 8 x 16B
        uint32_t adst = sm_u + (uint32_t)(pbuf * AFLOATS + tid * APITCH) * 4;
        #pragma unroll
        for (int j = 0; j < 8; j++)
            cp16(adst + j * 16, asrc + kk + j * 4);
        // B: 64 rows x 32 cols; 512 x 16B over 256 threads
        uint32_t bbase = sm_u + (uint32_t)(2 * AFLOATS + pbuf * BFLOATS) * 4;
        #pragma unroll
        for (int u = 0; u < 2; u++) {
            int idx = tid + u * 256;
            int n = idx >> 3, j = idx & 7;
            cp16(bbase + (uint32_t)(n * APITCH + j * 4) * 4,
                 curp + (size_t)n * DMODEL + kk + j * 4);
        }
        asm volatile("cp.async.commit_group;" ::: "memory");
    };

    load_chunk(0, 0);

    for (int it = 0; it < NCHUNK; it++) {
        if (it + 1 < NCHUNK) {
            load_chunk(it + 1, (it + 1) & 1);
            asm volatile("cp.async.wait_group 1;" ::: "memory");
        } else {
            asm volatile("cp.async.wait_group 0;" ::: "memory");
        }
        __syncthreads();

        const float* Ab = sm + (it & 1) * AFLOATS;
        const float* Bb = sm + 2 * AFLOATS + (it & 1) * BFLOATS;
        const float* Aw = Ab + (w * 32) * APITCH;

        #pragma unroll
        for (int k4 = 0; k4 < 4; k4++) {
            int k0 = k4 * 8;
            uint32_t a[2][4];
            #pragma unroll
            for (int i = 0; i < 2; i++) {
                int rb = 16 * i + g;
                a[i][0] = __float_as_uint(Aw[rb * APITCH + k0 + c]);
                a[i][1] = __float_as_uint(Aw[(rb + 8) * APITCH + k0 + c]);
                a[i][2] = __float_as_uint(Aw[rb * APITCH + k0 + c + 4]);
                a[i][3] = __float_as_uint(Aw[(rb + 8) * APITCH + k0 + c + 4]);
                // fragment-derived prev-row sumsq (full fp32 values)
                float f0 = __uint_as_float(a[i][0]), f1 = __uint_as_float(a[i][1]);
                float f2 = __uint_as_float(a[i][2]), f3 = __uint_as_float(a[i][3]);
                ssqA[i][0] += f0 * f0 + f2 * f2;
                ssqA[i][1] += f1 * f1 + f3 * f3;
            }
            #pragma unroll
            for (int j = 0; j < 8; j++) {
                uint32_t b0 = __float_as_uint(Bb[(8 * j + g) * APITCH + k0 + c]);
                uint32_t b1 = __float_as_uint(Bb[(8 * j + g) * APITCH + k0 + c + 4]);
                float fb0 = __uint_as_float(b0), fb1 = __uint_as_float(b1);
                ssqB[j] += fb0 * fb0 + fb1 * fb1;
                #pragma unroll
                for (int i = 0; i < 2; i++) {
                    asm volatile(
                        "mma.sync.aligned.m16n8k8.row.col.f32.tf32.tf32.f32 "
                        "{%0,%1,%2,%3}, {%4,%5,%6,%7}, {%8,%9}, {%0,%1,%2,%3};"
                        : "+f"(acc[i][j][0]), "+f"(acc[i][j][1]),
                          "+f"(acc[i][j][2]), "+f"(acc[i][j][3])
                        : "r"(a[i][0]), "r"(a[i][1]), "r"(a[i][2]), "r"(a[i][3]),
                          "r"(b0), "r"(b1));
                }
            }
        }
        __syncthreads();
    }

    // Reduce fragment sumsq over the 4 c-lanes (same g) -> row norms.
    #pragma unroll
    for (int i = 0; i < 2; i++)
        #pragma unroll
        for (int h = 0; h < 2; h++) {
            float v = ssqA[i][h];
            v += __shfl_xor_sync(0xFFFFFFFF, v, 1);
            v += __shfl_xor_sync(0xFFFFFFFF, v, 2);
            ssqA[i][h] = v;
        }
    if (c == 0) {
        #pragma unroll
        for (int i = 0; i < 2; i++) {
            sinvp[w * 32 + 16 * i + g]     = 1.0f / fmaxf(sqrtf(ssqA[i][0]), 1e-12f);
            sinvp[w * 32 + 16 * i + g + 8] = 1.0f / fmaxf(sqrtf(ssqA[i][1]), 1e-12f);
        }
    }
    #pragma unroll
    for (int j = 0; j < 8; j++) {
        float v = ssqB[j];
        v += __shfl_xor_sync(0xFFFFFFFF, v, 1);
        v += __shfl_xor_sync(0xFFFFFFFF, v, 2);
        if (w == 0 && c == 0)
            sinvq[8 * j + g] = 1.0f / fmaxf(sqrtf(v), 1e-12f);
    }
    __syncthreads();

    // per-warp col maxima over its 32 rows (scaled by inv prev norm)
    #pragma unroll
    for (int j = 0; j < 8; j++) {
        #pragma unroll
        for (int cc = 0; cc < 2; cc++) {
            float m = -INFINITY;
            #pragma unroll
            for (int i = 0; i < 2; i++) {
                int r0 = w * 32 + 16 * i + g;
                m = fmaxf(m, acc[i][j][cc] * sinvp[r0]);
                m = fmaxf(m, acc[i][j][cc + 2] * sinvp[r0 + 8]);
            }
            m = fmaxf(m, __shfl_xor_sync(0xFFFFFFFF, m, 4));
            m = fmaxf(m, __shfl_xor_sync(0xFFFFFFFF, m, 8));
            m = fmaxf(m, __shfl_xor_sync(0xFFFFFFFF, m, 16));
            if (g == 0) wcolmax[w][8 * j + 2 * c + cc] = m;
        }
    }
    __syncthreads();

    // split scores: split s owns warps 2s, 2s+1 (rows 64s..64s+63)
    {
        int s = tid >> 6, q = tid & 63;
        float m = fmaxf(wcolmax[2 * s][q], wcolmax[2 * s + 1][q]);
        float val = m * sinvq[q];
        #pragma unroll
        for (int o = 16; o > 0; o >>= 1)
            val += __shfl_xor_sync(0xFFFFFFFF, val, o);
        if (lane == 0) partial[w] = val;
    }
    __syncthreads();
    if (tid < 4) {
        int n_global = blockIdx.x * 4 + tid;
        if (n_global < csi)
            g_scores[b * 2048 + n_global] = partial[2 * tid] + partial[2 * tid + 1];
    }
}

// ---------------------------------------------------------------------------
// Kernel C: top-k + flat float32 output [indices | weights]
// ---------------------------------------------------------------------------
__global__ void topk_kernel(float* __restrict__ out, int csi, int kact, int B) {
    int b = blockIdx.x;
    int tid = threadIdx.x;
    __shared__ float s[2048];
    __shared__ float rv[256];
    __shared__ int   ri[256];
    __shared__ float topv[KTOP + 1];
    __shared__ int   topi[KTOP + 1];

    for (int i = tid; i < csi; i += 256) s[i] = g_scores[b * 2048 + i];
    __syncthreads();

    for (int t = 0; t < kact; t++) {
        float bv = -INFINITY;
        int bi = 0x7FFFFFFF;
        for (int i = tid; i < csi; i += 256) {
            float v = s[i];
            if (v > bv) { bv = v; bi = i; }
        }
        rv[tid] = bv; ri[tid] = bi;
        __syncthreads();
        for (int str = 128; str > 0; str >>= 1) {
            if (tid < str) {
                if (rv[tid + str] > rv[tid] ||
                    (rv[tid + str] == rv[tid] && ri[tid + str] < ri[tid])) {
                    rv[tid] = rv[tid + str];
                    ri[tid] = ri[tid + str];
                }
            }
            __syncthreads();
        }
        if (tid == 0) {
            topv[t] = rv[0];
            topi[t] = ri[0];
            s[ri[0]] = -INFINITY;
        }
        __syncthreads();
    }

    if (tid == 0) {
        int width = kact + 1;
        int woff = B * width;
        float mx = topv[0];
        for (int j = 0; j < kact; j++) {
            out[b * width + j]        = (float)topi[j];
            out[woff + b * width + j] = topv[j] / (mx + 1e-8f);
        }
        out[b * width + kact]        = (float)csi;
        out[woff + b * width + kact] = 1.0f;
    }
}

// ---------------------------------------------------------------------------
extern "C" void kernel_launch(void* const* d_in, const int* in_sizes, int n_in,
                              void* d_out, int out_size) {
    const float* emb = (const float*)d_in[0];
    long long total = (long long)in_sizes[0];
    int n_avail = (int)(total / ((long long)BATCH * DMODEL * SPLIT));
    int csi = n_avail - 1;
    int kact = csi < KTOP ? csi : KTOP;

    cudaFuncSetAttribute(sim_mma_kernel,
                         cudaFuncAttributeMaxDynamicSharedMemorySize, DYNB);

    int nb = (csi + 3) / 4;                 // 4 splits per CTA
    dim3 gB(nb, BATCH);
    sim_mma_kernel<<<gB, 256, DYNB>>>(emb, csi);

    topk_kernel<<<BATCH, 256>>>((float*)d_out, csi, kact, BATCH);
}

// round 17
// speedup vs baseline: 1.0038x; 1.0004x over previous
#include <cuda_runtime.h>
#include <math.h>
#include <stdint.h>

#define BATCH   2
#define DMODEL  1024
#define SPLIT   64
#define KTOP    7

#define CHUNK   32
#define NCHUNK  (DMODEL / CHUNK)      // 32
#define APITCH  36                    // floats per smem row (conflict-free)
#define AROWS   256                   // 4 splits per CTA
#define BROWS   64
#define AFLOATS (AROWS * APITCH)      // 9216
#define BFLOATS (BROWS * APITCH)      // 2304
#define DYNF    (2 * (AFLOATS + BFLOATS))
#define DYNB    (DYNF * 4)            // 92160 bytes

// Scratch (device globals; no allocation allowed)
__device__ float g_scores[BATCH * 2048];

__device__ __forceinline__ uint32_t smem_u32(const void* p) {
    uint32_t a;
    asm("{ .reg .u64 t; cvta.to.shared.u64 t, %1; cvt.u32.u64 %0, t; }"
        : "=r"(a) : "l"(p));
    return a;
}
__device__ __forceinline__ void cp16(uint32_t dst, const void* src) {
    asm volatile("cp.async.cg.shared.global [%0], [%1], 16;"
                 :: "r"(dst), "l"(src) : "memory");
}

// ---------------------------------------------------------------------------
// Kernel B: tf32 mma.sync GEMM. Per CTA: batch b, splits 4x..4x+3.
//   A = prev rows [row0 .. row0+255]  (M = 256)
//   B = cur rows  [0 .. 63]           (N = 64)
// Row norms (both prev and cur) are accumulated IN REGISTERS from the MMA
// fragments themselves (each warp's fragments cover its A sub-tile rows and
// all 64 B rows exactly once per K-chunk) -> no extra smem reads, no
// separate curnorm kernel.
// ---------------------------------------------------------------------------
__global__ void __launch_bounds__(256, 2)
sim_mma_kernel(const float* __restrict__ emb, int csi) {
    extern __shared__ float sm[];
    __shared__ float sinvp[256];      // prev-row inverse norms
    __shared__ float sinvq[64];       // cur-row inverse norms
    __shared__ float wcolmax[8][64];
    __shared__ float partial[8];

    int tid = threadIdx.x;
    int w = tid >> 5, lane = tid & 31, g = lane >> 2, c = lane & 3;
    int b = blockIdx.y;
    int row0 = blockIdx.x * 256;
    int maxrow = csi * SPLIT - 1;

    const float* base = emb + (size_t)b * (csi + 1) * SPLIT * DMODEL;
    const float* curp = base + (size_t)csi * SPLIT * DMODEL;

    // A source row for this thread (clamped; clamped rows land in splits
    // >= csi which are never emitted)
    int arow = row0 + tid;
    if (arow > maxrow) arow = maxrow;
    const float* asrc = base + (size_t)arow * DMODEL;

    uint32_t sm_u = smem_u32(sm);

    float acc[2][8][4];
    #pragma unroll
    for (int i = 0; i < 2; i++)
        #pragma unroll
        for (int j = 0; j < 8; j++)
            #pragma unroll
            for (int x = 0; x < 4; x++) acc[i][j][x] = 0.f;

    // fragment-derived sumsq accumulators
    float ssqA[2][2] = {{0.f, 0.f}, {0.f, 0.f}};   // rows w*32+16i+g, +8
    float ssqB[8];                                  // rows 8j+g
    #pragma unroll
    for (int j = 0; j < 8; j++) ssqB[j] = 0.f;

    auto load_chunk = [&](int it, int pbuf) {
        int kk = it * CHUNK;
        // A: 256 rows x 32 cols; thread = one row, 8 x 16B
        uint32_t adst = sm_u + (uint32_t)(pbuf * AFLOATS + tid * APITCH) * 4;
        #pragma unroll
        for (int j = 0; j < 8; j++)
            cp16(adst + j * 16, asrc + kk + j * 4);
        // B: 64 rows x 32 cols; 512 x 16B over 256 threads
        uint32_t bbase = sm_u + (uint32_t)(2 * AFLOATS + pbuf * BFLOATS) * 4;
        #pragma unroll
        for (int u = 0; u < 2; u++) {
            int idx = tid + u * 256;
            int n = idx >> 3, j = idx & 7;
            cp16(bbase + (uint32_t)(n * APITCH + j * 4) * 4,
                 curp + (size_t)n * DMODEL + kk + j * 4);
        }
        asm volatile("cp.async.commit_group;" ::: "memory");
    };

    load_chunk(0, 0);

    for (int it = 0; it < NCHUNK; it++) {
        if (it + 1 < NCHUNK) {
            load_chunk(it + 1, (it + 1) & 1);
            asm volatile("cp.async.wait_group 1;" ::: "memory");
        } else {
            asm volatile("cp.async.wait_group 0;" ::: "memory");
        }
        __syncthreads();

        const float* Ab = sm + (it & 1) * AFLOATS;
        const float* Bb = sm + 2 * AFLOATS + (it & 1) * BFLOATS;
        const float* Aw = Ab + (w * 32) * APITCH;

        #pragma unroll
        for (int k4 = 0; k4 < 4; k4++) {
            int k0 = k4 * 8;
            uint32_t a[2][4];
            #pragma unroll
            for (int i = 0; i < 2; i++) {
                int rb = 16 * i + g;
                a[i][0] = __float_as_uint(Aw[rb * APITCH + k0 + c]);
                a[i][1] = __float_as_uint(Aw[(rb + 8) * APITCH + k0 + c]);
                a[i][2] = __float_as_uint(Aw[rb * APITCH + k0 + c + 4]);
                a[i][3] = __float_as_uint(Aw[(rb + 8) * APITCH + k0 + c + 4]);
                // fragment-derived prev-row sumsq (full fp32 values)
                float f0 = __uint_as_float(a[i][0]), f1 = __uint_as_float(a[i][1]);
                float f2 = __uint_as_float(a[i][2]), f3 = __uint_as_float(a[i][3]);
                ssqA[i][0] += f0 * f0 + f2 * f2;
                ssqA[i][1] += f1 * f1 + f3 * f3;
            }
            #pragma unroll
            for (int j = 0; j < 8; j++) {
                uint32_t b0 = __float_as_uint(Bb[(8 * j + g) * APITCH + k0 + c]);
                uint32_t b1 = __float_as_uint(Bb[(8 * j + g) * APITCH + k0 + c + 4]);
                float fb0 = __uint_as_float(b0), fb1 = __uint_as_float(b1);
                ssqB[j] += fb0 * fb0 + fb1 * fb1;
                #pragma unroll
                for (int i = 0; i < 2; i++) {
                    asm volatile(
                        "mma.sync.aligned.m16n8k8.row.col.f32.tf32.tf32.f32 "
                        "{%0,%1,%2,%3}, {%4,%5,%6,%7}, {%8,%9}, {%0,%1,%2,%3};"
                        : "+f"(acc[i][j][0]), "+f"(acc[i][j][1]),
                          "+f"(acc[i][j][2]), "+f"(acc[i][j][3])
                        : "r"(a[i][0]), "r"(a[i][1]), "r"(a[i][2]), "r"(a[i][3]),
                          "r"(b0), "r"(b1));
                }
            }
        }
        __syncthreads();
    }

    // Reduce fragment sumsq over the 4 c-lanes (same g) -> row norms.
    #pragma unroll
    for (int i = 0; i < 2; i++)
        #pragma unroll
        for (int h = 0; h < 2; h++) {
            float v = ssqA[i][h];
            v += __shfl_xor_sync(0xFFFFFFFF, v, 1);
            v += __shfl_xor_sync(0xFFFFFFFF, v, 2);
            ssqA[i][h] = v;
        }
    if (c == 0) {
        #pragma unroll
        for (int i = 0; i < 2; i++) {
            sinvp[w * 32 + 16 * i + g]     = 1.0f / fmaxf(sqrtf(ssqA[i][0]), 1e-12f);
            sinvp[w * 32 + 16 * i + g + 8] = 1.0f / fmaxf(sqrtf(ssqA[i][1]), 1e-12f);
        }
    }
    #pragma unroll
    for (int j = 0; j < 8; j++) {
        float v = ssqB[j];
        v += __shfl_xor_sync(0xFFFFFFFF, v, 1);
        v += __shfl_xor_sync(0xFFFFFFFF, v, 2);
        if (w == 0 && c == 0)
            sinvq[8 * j + g] = 1.0f / fmaxf(sqrtf(v), 1e-12f);
    }
    __syncthreads();

    // per-warp col maxima over its 32 rows (scaled by inv prev norm)
    #pragma unroll
    for (int j = 0; j < 8; j++) {
        #pragma unroll
        for (int cc = 0; cc < 2; cc++) {
            float m = -INFINITY;
            #pragma unroll
            for (int i = 0; i < 2; i++) {
                int r0 = w * 32 + 16 * i + g;
                m = fmaxf(m, acc[i][j][cc] * sinvp[r0]);
                m = fmaxf(m, acc[i][j][cc + 2] * sinvp[r0 + 8]);
            }
            m = fmaxf(m, __shfl_xor_sync(0xFFFFFFFF, m, 4));
            m = fmaxf(m, __shfl_xor_sync(0xFFFFFFFF, m, 8));
            m = fmaxf(m, __shfl_xor_sync(0xFFFFFFFF, m, 16));
            if (g == 0) wcolmax[w][8 * j + 2 * c + cc] = m;
        }
    }
    __syncthreads();

    // split scores: split s owns warps 2s, 2s+1 (rows 64s..64s+63)
    {
        int s = tid >> 6, q = tid & 63;
        float m = fmaxf(wcolmax[2 * s][q], wcolmax[2 * s + 1][q]);
        float val = m * sinvq[q];
        #pragma unroll
        for (int o = 16; o > 0; o >>= 1)
            val += __shfl_xor_sync(0xFFFFFFFF, val, o);
        if (lane == 0) partial[w] = val;
    }
    __syncthreads();
    if (tid < 4) {
        int n_global = blockIdx.x * 4 + tid;
        if (n_global < csi)
            g_scores[b * 2048 + n_global] = partial[2 * tid] + partial[2 * tid + 1];
    }
}

// ---------------------------------------------------------------------------
// Kernel C: top-k + flat float32 output [indices | weights]
// ---------------------------------------------------------------------------
__global__ void topk_kernel(float* __restrict__ out, int csi, int kact, int B) {
    int b = blockIdx.x;
    int tid = threadIdx.x;
    __shared__ float s[2048];
    __shared__ float rv[256];
    __shared__ int   ri[256];
    __shared__ float topv[KTOP + 1];
    __shared__ int   topi[KTOP + 1];

    for (int i = tid; i < csi; i += 256) s[i] = g_scores[b * 2048 + i];
    __syncthreads();

    for (int t = 0; t < kact; t++) {
        float bv = -INFINITY;
        int bi = 0x7FFFFFFF;
        for (int i = tid; i < csi; i += 256) {
            float v = s[i];
            if (v > bv) { bv = v; bi = i; }
        }
        rv[tid] = bv; ri[tid] = bi;
        __syncthreads();
        for (int str = 128; str > 0; str >>= 1) {
            if (tid < str) {
                if (rv[tid + str] > rv[tid] ||
                    (rv[tid + str] == rv[tid] && ri[tid + str] < ri[tid])) {
                    rv[tid] = rv[tid + str];
                    ri[tid] = ri[tid + str];
                }
            }
            __syncthreads();
        }
        if (tid == 0) {
            topv[t] = rv[0];
            topi[t] = ri[0];
            s[ri[0]] = -INFINITY;
        }
        __syncthreads();
    }

    if (tid == 0) {
        int width = kact + 1;
        int woff = B * width;
        float mx = topv[0];
        for (int j = 0; j < kact; j++) {
            out[b * width + j]        = (float)topi[j];
            out[woff + b * width + j] = topv[j] / (mx + 1e-8f);
        }
        out[b * width + kact]        = (float)csi;
        out[woff + b * width + kact] = 1.0f;
    }
}

// ---------------------------------------------------------------------------
extern "C" void kernel_launch(void* const* d_in, const int* in_sizes, int n_in,
                              void* d_out, int out_size) {
    const float* emb = (const float*)d_in[0];
    long long total = (long long)in_sizes[0];
    int n_avail = (int)(total / ((long long)BATCH * DMODEL * SPLIT));
    int csi = n_avail - 1;
    int kact = csi < KTOP ? csi : KTOP;

    cudaFuncSetAttribute(sim_mma_kernel,
                         cudaFuncAttributeMaxDynamicSharedMemorySize, DYNB);

    int nb = (csi + 3) / 4;                 // 4 splits per CTA
    dim3 gB(nb, BATCH);
    sim_mma_kernel<<<gB, 256, DYNB>>>(emb, csi);

    topk_kernel<<<BATCH, 256>>>((float*)d_out, csi, kact, BATCH);
}